// round 10
// baseline (speedup 1.0000x reference)
#include <cuda_runtime.h>

#define N_ROWS 32768
#define K_ANCH 32
#define D_FEAT 128

#define XWB        256                 // xw-producer blocks per branch
#define XW_ROWS    (N_ROWS / XWB)      // 128 rows per producer block
#define GRID_X     (N_ROWS / 8)        // 4096... no: 8 rows/block -> 4096? (see launch)

// Scratch: xw table, readiness flags, finish counter. All zero-init at load;
// flags are self-reset by the last block each launch (deterministic).
__device__ float g_xw[2][N_ROWS];
__device__ int   g_done[2];
__device__ int   g_fin;

// Single launch. Block = 256 threads = 8 warp-rows. gridDim = (N/8, 2 branches).
//   os[n,d] = (1/K) sum_k dm[n,k] * x[idx[n,k], d]
//   op[n,k] = dm[n,k] * xw[idx[n,k]] + b,  xw[r] = dot(x[r,:], w)
// Blocks (y==0, x < 2*XWB) additionally produce a 128-row slice of xw first.
__global__ __launch_bounds__(256) void fused_kernel(
    const float* __restrict__ x1, const int* __restrict__ idx1, const float* __restrict__ dm1,
    const float* __restrict__ x2, const int* __restrict__ idx2, const float* __restrict__ dm2,
    const float* __restrict__ w,  const float* __restrict__ b_out,
    float* __restrict__ op1, float* __restrict__ os1,
    float* __restrict__ op2, float* __restrict__ os2)
{
    const int br = blockIdx.y;
    const float* __restrict__ x   = br ? x2   : x1;
    const int*   __restrict__ idx = br ? idx2 : idx1;
    const float* __restrict__ dm  = br ? dm2  : dm1;
    float*       __restrict__ op  = br ? op2  : op1;
    float*       __restrict__ os  = br ? os2  : os1;

    const int warp = threadIdx.x >> 5;
    const int lane = threadIdx.x & 31;
    const int n    = blockIdx.x * 8 + warp;

    // ---------- producer duty: first 2*XWB blocks of y==0 fill g_xw ----------
    if (blockIdx.y == 0 && blockIdx.x < 2 * XWB) {
        const int brp   = (blockIdx.x >= XWB) ? 1 : 0;
        const int chunk = blockIdx.x - brp * XWB;
        const float* __restrict__ xp = brp ? x2 : x1;
        const float4 wv = reinterpret_cast<const float4*>(w)[lane];
        const int base = chunk * XW_ROWS + warp * (XW_ROWS / 8);
        #pragma unroll 4
        for (int i = 0; i < XW_ROWS / 8; i++) {
            const int row = base + i;
            const float4 xv = reinterpret_cast<const float4*>(xp)[row * (D_FEAT / 4) + lane];
            float s = xv.x * wv.x + xv.y * wv.y + xv.z * wv.z + xv.w * wv.w;
            #pragma unroll
            for (int off = 16; off > 0; off >>= 1)
                s += __shfl_xor_sync(0xFFFFFFFFu, s, off);
            if (lane == 0) g_xw[brp][row] = s;
        }
        __syncthreads();
        if (threadIdx.x == 0) {
            __threadfence();
            atomicAdd(&g_done[brp], 1);
        }
    }

    // ---------- consumer: gather + os ----------
    __shared__ int4 s_meta[8][16];   // (off_2p, dm_2p, off_2p+1, dm_2p+1)

    const int   a = idx[n * K_ANCH + lane];    // coalesced; lane l owns k==l
    const float d = dm [n * K_ANCH + lane];    // coalesced
    {
        int2* dst = reinterpret_cast<int2*>(&s_meta[warp][0]) + lane;
        *dst = make_int2(a * (int)(D_FEAT * sizeof(float)), __float_as_int(d));
    }
    __syncwarp();

    const float b0 = __ldg(&b_out[0]);

    const char* __restrict__ xb = reinterpret_cast<const char*>(x);
    const int lane_byte = lane * 16;

    float4 acc = make_float4(0.f, 0.f, 0.f, 0.f);

    #pragma unroll
    for (int p = 0; p < 16; p++) {
        const int4 m = s_meta[warp][p];          // broadcast LDS.128
        const float d0 = __int_as_float(m.y);
        const float d1 = __int_as_float(m.w);
        const float4 v0 = __ldg(reinterpret_cast<const float4*>(xb + m.x + lane_byte));
        const float4 v1 = __ldg(reinterpret_cast<const float4*>(xb + m.z + lane_byte));
        acc.x = fmaf(d0, v0.x, acc.x);
        acc.y = fmaf(d0, v0.y, acc.y);
        acc.z = fmaf(d0, v0.z, acc.z);
        acc.w = fmaf(d0, v0.w, acc.w);
        acc.x = fmaf(d1, v1.x, acc.x);
        acc.y = fmaf(d1, v1.y, acc.y);
        acc.z = fmaf(d1, v1.z, acc.z);
        acc.w = fmaf(d1, v1.w, acc.w);
    }

    const float inv = 1.0f / (float)K_ANCH;
    acc.x *= inv; acc.y *= inv; acc.z *= inv; acc.w *= inv;
    reinterpret_cast<float4*>(os)[n * (D_FEAT / 4) + lane] = acc;   // coalesced 512B

    // ---------- wait for xw table (usually already complete), emit op ----------
    if (lane == 0) {
        volatile int* f = &g_done[br];
        while (*f < XWB) __nanosleep(64);
    }
    __syncwarp();
    __threadfence();   // acquire: order xw reads after flag observation

    const float xwv = g_xw[br][a];     // 4B lookup in 128KB table (L1-resident)
    op[n * K_ANCH + lane] = fmaf(d, xwv, b0);   // coalesced 128B

    // ---------- self-reset of flags by the globally-last block ----------
    __syncthreads();
    if (threadIdx.x == 0) {
        __threadfence();
        const int total = (int)(gridDim.x * gridDim.y);
        if (atomicAdd(&g_fin, 1) == total - 1) {
            g_done[0] = 0;
            g_done[1] = 0;
            g_fin     = 0;
            __threadfence();
        }
    }
}

extern "C" void kernel_launch(void* const* d_in, const int* in_sizes, int n_in,
                              void* d_out, int out_size) {
    const float* x1   = (const float*)d_in[0];
    const int*   idx1 = (const int*)  d_in[1];
    const float* dm1  = (const float*)d_in[2];
    const float* x2   = (const float*)d_in[3];
    const int*   idx2 = (const int*)  d_in[4];
    const float* dm2  = (const float*)d_in[5];
    const float* w    = (const float*)d_in[6];
    const float* b    = (const float*)d_in[7];

    float* out = (float*)d_out;
    float* op1 = out;                                       // [N, K]
    float* os1 = op1 + (size_t)N_ROWS * K_ANCH;             // [N, D]
    float* op2 = os1 + (size_t)N_ROWS * D_FEAT;             // [N, K]
    float* os2 = op2 + (size_t)N_ROWS * K_ANCH;             // [N, D]

    dim3 gg(N_ROWS / 8, 2);
    fused_kernel<<<gg, 256>>>(x1, idx1, dm1, x2, idx2, dm2, w, b,
                              op1, os1, op2, os2);
}

// round 12
// speedup vs baseline: 1.4095x; 1.4095x over previous
#include <cuda_runtime.h>

#define N_ROWS 32768
#define K_ANCH 32
#define D_FEAT 128

#define XWB     256                 // xw-producer blocks per branch
#define XW_ROWS (N_ROWS / XWB)      // 128 rows per producer block

// Scratch: xw table, readiness counters, finish counter. Zero at load;
// self-reset by the globally-last block each launch (deterministic).
__device__ float g_xw[2][N_ROWS];
__device__ int   g_done[2];
__device__ int   g_fin;

// Scoped sync primitives — NO gpu-scope fences (those flush L1D via CCTL.IVALL).
__device__ __forceinline__ int ld_acquire_gpu(const int* p) {
    int v;
    asm volatile("ld.acquire.gpu.global.b32 %0, [%1];" : "=r"(v) : "l"(p) : "memory");
    return v;
}
__device__ __forceinline__ void red_release_add(int* p, int v) {
    asm volatile("red.release.gpu.global.add.s32 [%0], %1;" :: "l"(p), "r"(v) : "memory");
}
__device__ __forceinline__ int atom_add_acq_rel(int* p, int v) {
    int old;
    asm volatile("atom.acq_rel.gpu.global.add.s32 %0, [%1], %2;"
                 : "=r"(old) : "l"(p), "r"(v) : "memory");
    return old;
}
// L2-coherent load: reads the coherence point the release/acquire pair uses.
// (NOT __ldg/.nc — g_xw is written during this kernel, .nc may return stale data.)
__device__ __forceinline__ float ld_cg(const float* p) {
    float v;
    asm volatile("ld.global.cg.f32 %0, [%1];" : "=f"(v) : "l"(p) : "memory");
    return v;
}

// Single launch. Block = 256 threads = 8 warp-rows. gridDim = (N/8, 2 branches).
//   os[n,d] = (1/K) sum_k dm[n,k] * x[idx[n,k], d]
//   op[n,k] = dm[n,k] * xw[idx[n,k]] + b,   xw[r] = dot(x[r,:], w)
// Blocks (y==0, x < 2*XWB) additionally produce a 128-row slice of xw first.
__global__ __launch_bounds__(256) void fused_kernel(
    const float* __restrict__ x1, const int* __restrict__ idx1, const float* __restrict__ dm1,
    const float* __restrict__ x2, const int* __restrict__ idx2, const float* __restrict__ dm2,
    const float* __restrict__ w,  const float* __restrict__ b_out,
    float* __restrict__ op1, float* __restrict__ os1,
    float* __restrict__ op2, float* __restrict__ os2)
{
    const int br = blockIdx.y;
    const float* __restrict__ x   = br ? x2   : x1;
    const int*   __restrict__ idx = br ? idx2 : idx1;
    const float* __restrict__ dm  = br ? dm2  : dm1;
    float*       __restrict__ op  = br ? op2  : op1;
    float*       __restrict__ os  = br ? os2  : os1;

    const int warp = threadIdx.x >> 5;
    const int lane = threadIdx.x & 31;
    const int n    = blockIdx.x * 8 + warp;

    // ---------- producer duty: first 2*XWB blocks (all wave-1) fill g_xw ----------
    if (blockIdx.y == 0 && blockIdx.x < 2 * XWB) {
        const int brp   = (blockIdx.x >= XWB) ? 1 : 0;
        const int chunk = blockIdx.x - brp * XWB;
        const float* __restrict__ xp = brp ? x2 : x1;
        const float4 wv = reinterpret_cast<const float4*>(w)[lane];
        const int base = chunk * XW_ROWS + warp * (XW_ROWS / 8);
        #pragma unroll
        for (int i = 0; i < XW_ROWS / 8; i++) {
            const int row = base + i;
            const float4 xv = reinterpret_cast<const float4*>(xp)[row * (D_FEAT / 4) + lane];
            float s = xv.x * wv.x + xv.y * wv.y + xv.z * wv.z + xv.w * wv.w;
            #pragma unroll
            for (int off = 16; off > 0; off >>= 1)
                s += __shfl_xor_sync(0xFFFFFFFFu, s, off);
            if (lane == 0) g_xw[brp][row] = s;
        }
        __syncthreads();                       // block's xw writes complete
        if (threadIdx.x == 0)
            red_release_add(&g_done[brp], 1);  // publish (release, no L1 flush)
    }

    // ---------- consumer: gather + os ----------
    __shared__ int4 s_meta[8][16];   // (off_2p, dm_2p, off_2p+1, dm_2p+1)

    const int   a = idx[n * K_ANCH + lane];    // coalesced; lane l owns k==l
    const float d = dm [n * K_ANCH + lane];    // coalesced
    {
        int2* dst = reinterpret_cast<int2*>(&s_meta[warp][0]) + lane;
        *dst = make_int2(a * (int)(D_FEAT * sizeof(float)), __float_as_int(d));
    }
    __syncwarp();

    const float b0 = __ldg(&b_out[0]);

    const char* __restrict__ xb = reinterpret_cast<const char*>(x);
    const int lane_byte = lane * 16;

    float4 acc = make_float4(0.f, 0.f, 0.f, 0.f);

    #pragma unroll
    for (int p = 0; p < 16; p++) {
        const int4 m = s_meta[warp][p];          // broadcast LDS.128
        const float d0 = __int_as_float(m.y);
        const float d1 = __int_as_float(m.w);
        const float4 v0 = __ldg(reinterpret_cast<const float4*>(xb + m.x + lane_byte));
        const float4 v1 = __ldg(reinterpret_cast<const float4*>(xb + m.z + lane_byte));
        acc.x = fmaf(d0, v0.x, acc.x);
        acc.y = fmaf(d0, v0.y, acc.y);
        acc.z = fmaf(d0, v0.z, acc.z);
        acc.w = fmaf(d0, v0.w, acc.w);
        acc.x = fmaf(d1, v1.x, acc.x);
        acc.y = fmaf(d1, v1.y, acc.y);
        acc.z = fmaf(d1, v1.z, acc.z);
        acc.w = fmaf(d1, v1.w, acc.w);
    }

    const float inv = 1.0f / (float)K_ANCH;
    acc.x *= inv; acc.y *= inv; acc.z *= inv; acc.w *= inv;
    reinterpret_cast<float4*>(os)[n * (D_FEAT / 4) + lane] = acc;   // coalesced 512B

    // ---------- wait for xw table (one acquire-poller per block), emit op ----------
    if (threadIdx.x == 0) {
        int spins = 0;
        while (ld_acquire_gpu(&g_done[br]) < XWB) {
            if (++spins > 4) __nanosleep(128);
        }
    }
    __syncthreads();   // block-wide ordering after thread0's acquire

    const float xwv = ld_cg(&g_xw[br][a]);        // L2-coherent 4B lookup
    op[n * K_ANCH + lane] = fmaf(d, xwv, b0);     // coalesced 128B

    // ---------- self-reset of flags by the globally-last block ----------
    if (threadIdx.x == 0) {
        const int total = (int)(gridDim.x * gridDim.y);
        if (atom_add_acq_rel(&g_fin, 1) == total - 1) {
            g_done[0] = 0;
            g_done[1] = 0;
            g_fin     = 0;
        }
    }
}

extern "C" void kernel_launch(void* const* d_in, const int* in_sizes, int n_in,
                              void* d_out, int out_size) {
    const float* x1   = (const float*)d_in[0];
    const int*   idx1 = (const int*)  d_in[1];
    const float* dm1  = (const float*)d_in[2];
    const float* x2   = (const float*)d_in[3];
    const int*   idx2 = (const int*)  d_in[4];
    const float* dm2  = (const float*)d_in[5];
    const float* w    = (const float*)d_in[6];
    const float* b    = (const float*)d_in[7];

    float* out = (float*)d_out;
    float* op1 = out;                                       // [N, K]
    float* os1 = op1 + (size_t)N_ROWS * K_ANCH;             // [N, D]
    float* op2 = os1 + (size_t)N_ROWS * D_FEAT;             // [N, K]
    float* os2 = op2 + (size_t)N_ROWS * K_ANCH;             // [N, D]

    dim3 gg(N_ROWS / 8, 2);
    fused_kernel<<<gg, 256>>>(x1, idx1, dm1, x2, idx2, dm2, w, b,
                              op1, os1, op2, os2);
}

// round 13
// speedup vs baseline: 1.4488x; 1.0278x over previous
#include <cuda_runtime.h>

#define N_ROWS 32768
#define K_ANCH 32
#define D_FEAT 128

// Fold two composites at lane-xor offset `off` (natural k order, LSB-first).
// After all 5 folds, lane l holds the full cross-lane sum for k == l.
__device__ __forceinline__ float warp_fold(float a, float b, int off, int lane) {
    float r = (lane & off) ? a : b;
    float s = __shfl_xor_sync(0xFFFFFFFFu, r, off);
    return ((lane & off) ? b : a) + s;
}

// Single fused kernel, both branches (blockIdx.y). Warp per row n, float4 lane.
//   os[n,d]  = (1/K) sum_k dm[n,k] * x[idx[n,k], d]
//   op[n,k]  = dm[n,k] * dot(x[idx[n,k],:], w) + b      (in-register fold)
__global__ __launch_bounds__(256) void fused_kernel(
    const float* __restrict__ x1, const int* __restrict__ idx1, const float* __restrict__ dm1,
    const float* __restrict__ x2, const int* __restrict__ idx2, const float* __restrict__ dm2,
    const float* __restrict__ w,  const float* __restrict__ b_out,
    float* __restrict__ op1, float* __restrict__ os1,
    float* __restrict__ op2, float* __restrict__ os2)
{
    const int br = blockIdx.y;
    const float* __restrict__ x   = br ? x2   : x1;
    const int*   __restrict__ idx = br ? idx2 : idx1;
    const float* __restrict__ dm  = br ? dm2  : dm1;
    float*       __restrict__ op  = br ? op2  : op1;
    float*       __restrict__ os  = br ? os2  : os1;

    const int warp = threadIdx.x >> 5;
    const int lane = threadIdx.x & 31;
    const int n    = blockIdx.x * 8 + warp;

    // Metadata for 2 k's per int4: (off_2p, dm_2p, off_2p+1, dm_2p+1).
    __shared__ int4 s_meta[8][16];

    // Lane l owns metadata for k == l.
    const int   a = idx[n * K_ANCH + lane];    // coalesced
    const float d = dm [n * K_ANCH + lane];    // coalesced
    {
        int2* dst = reinterpret_cast<int2*>(&s_meta[warp][0]) + lane;
        *dst = make_int2(a * (int)(D_FEAT * sizeof(float)), __float_as_int(d));
    }
    __syncwarp();

    const float b0 = __ldg(&b_out[0]);

    // This lane's 4-wide slice of w.
    const float4 w4 = reinterpret_cast<const float4*>(w)[lane];

    // Loop-invariant gather base: one IADD per load inside the loop.
    const char* __restrict__ xbl =
        reinterpret_cast<const char*>(x) + lane * 16;

    // Two independent accumulation chains (even/odd k) — halves FMA RAW chain.
    float4 accA = make_float4(0.f, 0.f, 0.f, 0.f);
    float4 accB = make_float4(0.f, 0.f, 0.f, 0.f);

    float stk[6];
    int sp = 0;

    #pragma unroll
    for (int p = 0; p < 16; p++) {
        const int4 m = s_meta[warp][p];          // broadcast LDS.128
        const float d0 = __int_as_float(m.y);
        const float d1 = __int_as_float(m.w);
        const float4 v0 = __ldg(reinterpret_cast<const float4*>(xbl + m.x));
        const float4 v1 = __ldg(reinterpret_cast<const float4*>(xbl + m.z));

        // k = 2p : accA = fma(d0, v0, accA); o = d0 * dot(v0, w)
        {
            accA.x = fmaf(d0, v0.x, accA.x);
            accA.y = fmaf(d0, v0.y, accA.y);
            accA.z = fmaf(d0, v0.z, accA.z);
            accA.w = fmaf(d0, v0.w, accA.w);
            float o = v0.x * w4.x;
            o = fmaf(v0.y, w4.y, o);
            o = fmaf(v0.z, w4.z, o);
            o = fmaf(v0.w, w4.w, o);
            stk[sp++] = d0 * o;
        }
        // k = 2p+1 : accB chain
        {
            accB.x = fmaf(d1, v1.x, accB.x);
            accB.y = fmaf(d1, v1.y, accB.y);
            accB.z = fmaf(d1, v1.z, accB.z);
            accB.w = fmaf(d1, v1.w, accB.w);
            float o = v1.x * w4.x;
            o = fmaf(v1.y, w4.y, o);
            o = fmaf(v1.z, w4.z, o);
            o = fmaf(v1.w, w4.w, o);
            stk[sp++] = d1 * o;
        }

        // Eager binary-counter folding, LSB-first.
        const int i1 = 2 * p + 2;   // items completed
        #pragma unroll
        for (int j = 0; j < 5; j++) {
            if ((i1 & ((2 << j) - 1)) == 0) {
                const int off = 1 << j;
                sp -= 2;
                stk[sp] = warp_fold(stk[sp], stk[sp + 1], off, lane);
                sp += 1;
            }
        }
    }

    // stk[0]: lane l holds op-value for k == l (pre-bias).
    const float opv = stk[0] + b0;

    const float inv = 1.0f / (float)K_ANCH;
    float4 acc;
    acc.x = (accA.x + accB.x) * inv;
    acc.y = (accA.y + accB.y) * inv;
    acc.z = (accA.z + accB.z) * inv;
    acc.w = (accA.w + accB.w) * inv;

    reinterpret_cast<float4*>(os)[n * (D_FEAT / 4) + lane] = acc;   // coalesced 512B
    op[n * K_ANCH + lane] = opv;                                    // coalesced 128B
}

extern "C" void kernel_launch(void* const* d_in, const int* in_sizes, int n_in,
                              void* d_out, int out_size) {
    const float* x1   = (const float*)d_in[0];
    const int*   idx1 = (const int*)  d_in[1];
    const float* dm1  = (const float*)d_in[2];
    const float* x2   = (const float*)d_in[3];
    const int*   idx2 = (const int*)  d_in[4];
    const float* dm2  = (const float*)d_in[5];
    const float* w    = (const float*)d_in[6];
    const float* b    = (const float*)d_in[7];

    float* out = (float*)d_out;
    float* op1 = out;                                       // [N, K]
    float* os1 = op1 + (size_t)N_ROWS * K_ANCH;             // [N, D]
    float* op2 = os1 + (size_t)N_ROWS * D_FEAT;             // [N, K]
    float* os2 = op2 + (size_t)N_ROWS * K_ANCH;             // [N, D]

    dim3 gg(N_ROWS / 8, 2);
    fused_kernel<<<gg, 256>>>(x1, idx1, dm1, x2, idx2, dm2, w, b,
                              op1, os1, op2, os2);
}

// round 14
// speedup vs baseline: 1.7137x; 1.1829x over previous
#include <cuda_runtime.h>

#define N_ROWS 32768
#define K_ANCH 32
#define D_FEAT 128

// Fold two composites at lane-xor offset `off`. `a` must be the composite
// whose k-set has the `off` bit clear (the OLDER one in natural order,
// folding LSB-first). After all 5 folds, lane l holds the sum for k == l.
__device__ __forceinline__ float warp_fold(float a, float b, int off, int lane) {
    float r = (lane & off) ? a : b;
    float s = __shfl_xor_sync(0xFFFFFFFFu, r, off);
    return ((lane & off) ? b : a) + s;
}

// Single fused kernel, both branches (blockIdx.y). Warp per row n, float4 lane.
//   os[n,d]  = (1/K) sum_k dm[n,k] * x[idx[n,k], d]
//   op[n,k]  = dm[n,k] * dot(x[idx[n,k],:], w) + b      (in-register fold)
// Metadata broadcast via LDS.128 (1 slot / 2 k's) to minimize LSU-pipe ops.
__global__ __launch_bounds__(256) void fused_kernel(
    const float* __restrict__ x1, const int* __restrict__ idx1, const float* __restrict__ dm1,
    const float* __restrict__ x2, const int* __restrict__ idx2, const float* __restrict__ dm2,
    const float* __restrict__ w,  const float* __restrict__ b_out,
    float* __restrict__ op1, float* __restrict__ os1,
    float* __restrict__ op2, float* __restrict__ os2)
{
    const int br = blockIdx.y;
    const float* __restrict__ x   = br ? x2   : x1;
    const int*   __restrict__ idx = br ? idx2 : idx1;
    const float* __restrict__ dm  = br ? dm2  : dm1;
    float*       __restrict__ op  = br ? op2  : op1;
    float*       __restrict__ os  = br ? os2  : os1;

    const int warp = threadIdx.x >> 5;
    const int lane = threadIdx.x & 31;
    const int n    = blockIdx.x * 8 + warp;

    // Metadata for 2 k's per int4: (off_2p, dm_2p, off_2p+1, dm_2p+1).
    __shared__ int4 s_meta[8][16];

    // Lane l owns metadata for k == l.
    const int   a = idx[n * K_ANCH + lane];    // coalesced
    const float d = dm [n * K_ANCH + lane];    // coalesced
    {
        int2* dst = reinterpret_cast<int2*>(&s_meta[warp][0]) + lane;
        *dst = make_int2(a * (int)(D_FEAT * sizeof(float)), __float_as_int(d));
    }
    __syncwarp();

    // This lane's 4-wide slice of w.
    const float4 w4 = reinterpret_cast<const float4*>(w)[lane];

    const char* __restrict__ xb = reinterpret_cast<const char*>(x);
    const int lane_byte = lane * 16;

    float4 acc = make_float4(0.f, 0.f, 0.f, 0.f);

    float stk[6];
    int sp = 0;

    #pragma unroll
    for (int p = 0; p < 16; p++) {
        const int4 m = s_meta[warp][p];          // broadcast LDS.128 (1 slot)
        const float d0 = __int_as_float(m.y);
        const float d1 = __int_as_float(m.w);
        const float4 v0 = __ldg(reinterpret_cast<const float4*>(xb + m.x + lane_byte));
        const float4 v1 = __ldg(reinterpret_cast<const float4*>(xb + m.z + lane_byte));

        // k = 2p
        {
            const float tx = d0 * v0.x, ty = d0 * v0.y, tz = d0 * v0.z, tw = d0 * v0.w;
            acc.x += tx; acc.y += ty; acc.z += tz; acc.w += tw;
            float o = tx * w4.x;
            o = fmaf(ty, w4.y, o); o = fmaf(tz, w4.z, o); o = fmaf(tw, w4.w, o);
            stk[sp++] = o;
        }
        // k = 2p+1
        {
            const float tx = d1 * v1.x, ty = d1 * v1.y, tz = d1 * v1.z, tw = d1 * v1.w;
            acc.x += tx; acc.y += ty; acc.z += tz; acc.w += tw;
            float o = tx * w4.x;
            o = fmaf(ty, w4.y, o); o = fmaf(tz, w4.z, o); o = fmaf(tw, w4.w, o);
            stk[sp++] = o;
        }

        // Eager binary-counter folding over natural k order, LSB-first:
        // after item i (i = 2p+1 here), fold depth j iff (i+1) % 2^(j+1) == 0.
        const int i1 = 2 * p + 2;   // items completed
        #pragma unroll
        for (int j = 0; j < 5; j++) {
            if ((i1 & ((2 << j) - 1)) == 0) {
                const int off = 1 << j;
                sp -= 2;
                stk[sp] = warp_fold(stk[sp], stk[sp + 1], off, lane);
                sp += 1;
            }
        }
    }

    // stk[0]: lane l holds op-value for k == l (pre-bias).
    const float opv = stk[0] + __ldg(&b_out[0]);

    const float inv = 1.0f / (float)K_ANCH;
    acc.x *= inv; acc.y *= inv; acc.z *= inv; acc.w *= inv;

    reinterpret_cast<float4*>(os)[n * (D_FEAT / 4) + lane] = acc;   // coalesced 512B
    op[n * K_ANCH + lane] = opv;                                    // coalesced 128B
}

extern "C" void kernel_launch(void* const* d_in, const int* in_sizes, int n_in,
                              void* d_out, int out_size) {
    const float* x1   = (const float*)d_in[0];
    const int*   idx1 = (const int*)  d_in[1];
    const float* dm1  = (const float*)d_in[2];
    const float* x2   = (const float*)d_in[3];
    const int*   idx2 = (const int*)  d_in[4];
    const float* dm2  = (const float*)d_in[5];
    const float* w    = (const float*)d_in[6];
    const float* b    = (const float*)d_in[7];

    float* out = (float*)d_out;
    float* op1 = out;                                       // [N, K]
    float* os1 = op1 + (size_t)N_ROWS * K_ANCH;             // [N, D]
    float* op2 = os1 + (size_t)N_ROWS * D_FEAT;             // [N, K]
    float* os2 = op2 + (size_t)N_ROWS * K_ANCH;             // [N, D]

    dim3 gg(N_ROWS / 8, 2);
    fused_kernel<<<gg, 256>>>(x1, idx1, dm1, x2, idx2, dm2, w, b,
                              op1, os1, op2, os2);
}